// round 11
// baseline (speedup 1.0000x reference)
#include <cuda_runtime.h>

typedef unsigned long long u64;

#define NL    16
#define CC    128
#define CP    (CC / 2)
#define EE    10
#define P3C   23
#define P2C   4
#define MAXN  4096
#define MB    16
#define SPLIT 4
#define NPOS  1120
#define NSLOT 160
#define NACT  136
#define PCB   (CC / 8 * EE)                // 160 coeff blocks
#define SYMB  ((NPOS * P3C + 255) / 256)   // 101 sym blocks
#define CONB  (CP * EE)                    // 640 contract blocks (4 groups each)

// __device__ globals = sanctioned scratch.
__device__ float g_S[(size_t)EE * CC * NPOS];
__device__ float g_Q[EE * CC * NSLOT];
__device__ float g_L[EE * CC * NL];
__device__ float g_U3S[NPOS * P3C];
__device__ __align__(16) float g_xT[(size_t)CP * MAXN * NL * 2]; // [cp][gpos][i][2ch]
__device__ int g_binsg[MAXN];
__device__ int g_pos[MAXN];
__device__ int g_counts[EE];
__device__ int g_offs[EE];
// phase counters (self-resetting; statically zero-initialized)
__device__ int g_sym_done;
__device__ int g_bin_done;
__device__ int g_coeff_done;
__device__ int g_trans_done;
__device__ int g_fin;

// ---- packed f32x2 helpers -------------------------------------------------
__device__ __forceinline__ u64 fma2(u64 a, u64 b, u64 c) {
    u64 d; asm("fma.rn.f32x2 %0, %1, %2, %3;" : "=l"(d) : "l"(a), "l"(b), "l"(c)); return d;
}
__device__ __forceinline__ u64 mul2(u64 a, u64 b) {
    u64 d; asm("mul.rn.f32x2 %0, %1, %2;" : "=l"(d) : "l"(a), "l"(b)); return d;
}
__device__ __forceinline__ u64 add2(u64 a, u64 b) {
    u64 d; asm("add.rn.f32x2 %0, %1, %2;" : "=l"(d) : "l"(a), "l"(b)); return d;
}
__device__ __forceinline__ u64 pack2(float lo, float hi) {
    u64 d; asm("mov.b64 %0, {%1, %2};" : "=l"(d) : "f"(lo), "f"(hi)); return d;
}
__device__ __forceinline__ void barsync64(int id) {
    asm volatile("bar.sync %0, 64;" :: "r"(id) : "memory");
}

__device__ __forceinline__ void slot_ab(int s, int& a, int& b) {
    a = 0; b = 0;
    int off = 0;
#pragma unroll
    for (int aa = 15; aa >= 0; aa--) {
        int cnt = 16 - aa;
        if (s >= off && s < off + cnt) { a = aa; b = aa + (s - off); }
        off += cnt;
    }
}

__device__ __forceinline__ float u3at(const float* U3, int d0, int d1, int d2, int k) {
    return U3[((d0 * NL + d1) * NL + d2) * P3C + k];
}

// ---------------------------------------------------------------------------
// Fused mega-kernel. Phases by ascending blockIdx; consumers spin only on
// lower-ID producers (forward-only deps -> no deadlock).
// ---------------------------------------------------------------------------
__global__ __launch_bounds__(256, 2) void fused_kernel(const float* __restrict__ U3,
                                                       const float* __restrict__ W3,
                                                       const float* __restrict__ U2,
                                                       const float* __restrict__ W2,
                                                       const float* __restrict__ U1,
                                                       const float* __restrict__ W1,
                                                       const float* __restrict__ x,
                                                       const int* __restrict__ at,
                                                       float* __restrict__ out, int N) {
    const int bx  = blockIdx.x;
    const int tid = threadIdx.x;

    // ======================= phase 1a: sym U3 ==============================
    if (bx < SYMB) {
        const int idx = bx * 256 + tid;
        if (idx < NPOS * P3C) {
            const int p = idx / P3C;
            const int k = idx - p * P3C;
            int base, ch;
            if      (p < 512)  { ch = 0; base = 0;    }
            else if (p < 800)  { ch = 1; base = 512;  }
            else if (p < 992)  { ch = 2; base = 800;  }
            else if (p < 1088) { ch = 3; base = 992;  }
            else               { ch = 4; base = 1088; }
            const int rel = p - base;
            const int j = rel >> 5;
            const int l = rel & 31;
            const int s = ch * 32 + l;
            float val = 0.f;
            if (s < NACT) {
                int a, b; slot_ab(s, a, b);
                const int i = j;
                if (i <= a) {
                    float sum = u3at(U3, i, a, b, k) + u3at(U3, i, b, a, k)
                              + u3at(U3, a, i, b, k) + u3at(U3, a, b, i, k)
                              + u3at(U3, b, i, a, k) + u3at(U3, b, a, i, k);
                    float r = (i == a && a == b) ? 6.f : ((i == a || a == b) ? 2.f : 1.f);
                    val = sum / r;
                }
            }
            g_U3S[idx] = val;
        }
        __syncthreads();
        if (tid == 0) { __threadfence(); atomicAdd(&g_sym_done, 1); }
        return;
    }

    // ======================= phase 1b: binning =============================
    if (bx == SYMB) {
        __shared__ int ts[MAXN];
        __shared__ int wcnt[8 * EE];
        __shared__ int cur[8 * EE];
        const int w = tid >> 5, lane = tid & 31;
        for (int idx = tid; idx < N; idx += 256) ts[idx] = at[idx];
        if (tid < 8 * EE) wcnt[tid] = 0;
        __syncthreads();
        const int D  = (((N + 7) / 8) + 31) & ~31;
        const int lo = w * D, hi = min(N, lo + D);
        for (int base = lo; base < hi; base += 32) {
            const int idx = base + lane;
            const int t = (idx < hi) ? ts[idx] : -1;
            unsigned mm = __match_any_sync(0xffffffffu, t);
            if (t >= 0 && lane == (__ffs(mm) - 1))
                atomicAdd(&wcnt[w * EE + t], __popc(mm));
        }
        __syncthreads();
        if (tid == 0) {
            int acc = 0;
            for (int t = 0; t < EE; t++) {
                g_offs[t] = acc;
                int run = acc;
                for (int ww = 0; ww < 8; ww++) { cur[ww * EE + t] = run; run += wcnt[ww * EE + t]; }
                g_counts[t] = run - acc;
                acc = run;
            }
        }
        __syncthreads();
        for (int base = lo; base < hi; base += 32) {
            const int idx = base + lane;
            const int t = (idx < hi) ? ts[idx] : -1;
            unsigned mm = __match_any_sync(0xffffffffu, t);
            const int leader = __ffs(mm) - 1;
            const int rank = __popc(mm & ((1u << lane) - 1u));
            int baseoff = 0;
            if (t >= 0 && lane == leader) baseoff = atomicAdd(&cur[w * EE + t], __popc(mm));
            baseoff = __shfl_sync(0xffffffffu, baseoff, leader);
            if (t >= 0) {
                const int gp = baseoff + rank;
                g_binsg[gp] = idx;
                g_pos[idx]  = gp;
            }
        }
        __syncthreads();
        if (tid == 0) { __threadfence(); atomicExch(&g_bin_done, 1); }
        return;
    }

    // ======================= phase 2a: coeff contraction ===================
    if (bx < SYMB + 1 + PCB) {
        if (tid == 0) {
            while (atomicAdd(&g_sym_done, 0) < SYMB) __nanosleep(128);
            __threadfence();
        }
        __syncthreads();

        __shared__ float sm[NL * 132];
        const int bc = bx - (SYMB + 1);
        const int c0 = (bc & 15) * 8;
        const int e  = bc >> 4;
        float* W3s = sm;
        float* W2s = sm + P3C * 8;
        float* W1s = W2s + P2C * 8;
        for (int idx = tid; idx < P3C * 8; idx += 256) {
            int k = idx >> 3, cl = idx & 7;
            W3s[idx] = W3[(e * P3C + k) * CC + c0 + cl];
        }
        if (tid < P2C * 8) {
            int k = tid >> 3, cl = tid & 7;
            W2s[tid] = W2[(e * P2C + k) * CC + c0 + cl];
        }
        if (tid < 8) W1s[tid] = W1[e * CC + c0 + tid];
        __syncthreads();

        for (int p = tid; p < NPOS; p += 256) {
            float u[P3C];
#pragma unroll
            for (int k = 0; k < P3C; k++) u[k] = g_U3S[p * P3C + k];
#pragma unroll
            for (int cl = 0; cl < 8; cl++) {
                float acc = 0.f;
#pragma unroll
                for (int k = 0; k < P3C; k++) acc += u[k] * W3s[k * 8 + cl];
                g_S[((size_t)(e * CC + c0 + cl)) * NPOS + p] = acc;
            }
        }
        if (tid < NSLOT) {
            const int s = tid;
            int a = 0, b = 0;
            const bool act = (s < NACT);
            if (act) slot_ab(s, a, b);
#pragma unroll
            for (int cl = 0; cl < 8; cl++) {
                float q = 0.f;
                if (act) {
                    float Bab = 0.f, Bba = 0.f;
#pragma unroll
                    for (int k = 0; k < P2C; k++) {
                        Bab += U2[(a * NL + b) * P2C + k] * W2s[k * 8 + cl];
                        Bba += U2[(b * NL + a) * P2C + k] * W2s[k * 8 + cl];
                    }
                    q = (a == b) ? Bab : (Bab + Bba);
                }
                g_Q[(size_t)(e * CC + c0 + cl) * NSLOT + s] = q;
            }
        }
        if (tid < NL) {
#pragma unroll
            for (int cl = 0; cl < 8; cl++)
                g_L[(size_t)(e * CC + c0 + cl) * NL + tid] = U1[tid] * W1s[cl];
        }
        __syncthreads();
        if (tid == 0) { __threadfence(); atomicAdd(&g_coeff_done, 1); }
        return;
    }

    // ======================= phase 2b: transpose ===========================
    if (bx < SYMB + 1 + PCB + N) {
        if (tid == 0) {
            while (atomicAdd(&g_bin_done, 0) == 0) __nanosleep(128);
            __threadfence();
        }
        __syncthreads();

        __shared__ float sm[NL * 132];
        const int n = bx - (SYMB + 1 + PCB);
        const float4* xin = (const float4*)(x + (size_t)n * NL * CC);
#pragma unroll
        for (int q = 0; q < 2; q++) {
            const int v  = q * 256 + tid;
            const int i  = v >> 5;
            const int f4 = v & 31;
            *(float4*)(sm + i * 132 + f4 * 4) = xin[v];
        }
        __syncthreads();
        const int gp = g_pos[n];
        const int cp = tid >> 2;
        const int q  = tid & 3;
        const int c0 = 2 * cp;
        float* orow = g_xT + ((size_t)cp * MAXN + gp) * 32 + q * 8;
        float4 oA, oB;
        oA.x = sm[(4 * q + 0) * 132 + c0]; oA.y = sm[(4 * q + 0) * 132 + c0 + 1];
        oA.z = sm[(4 * q + 1) * 132 + c0]; oA.w = sm[(4 * q + 1) * 132 + c0 + 1];
        oB.x = sm[(4 * q + 2) * 132 + c0]; oB.y = sm[(4 * q + 2) * 132 + c0 + 1];
        oB.z = sm[(4 * q + 3) * 132 + c0]; oB.w = sm[(4 * q + 3) * 132 + c0 + 1];
        ((float4*)orow)[0] = oA;
        ((float4*)orow)[1] = oB;
        __syncthreads();
        if (tid == 0) { __threadfence(); atomicAdd(&g_trans_done, 1); }
        return;
    }

    // ======================= phase 3: contract =============================
    {
        if (tid == 0) {
            while (atomicAdd(&g_trans_done, 0) < N || atomicAdd(&g_coeff_done, 0) < PCB)
                __nanosleep(128);
            __threadfence();
        }
        __syncthreads();

        const int cb = bx - (SYMB + 1 + PCB + N);
        const int e  = cb / CP;
        const int cp = cb - e * CP;
        const int g  = tid >> 6;        // group = z split
        const int t  = tid & 63;
        const int w  = t >> 5, lane = t & 31;
        const int z  = g;

        __shared__ __align__(16) float xs[SPLIT][MB][32];
        __shared__ u64 red[SPLIT][MB][2];

        const int count  = g_counts[e];
        const int goff   = g_offs[e];
        const int ntiles = (count + MB - 1) / MB;
        const int tpc    = (ntiles + SPLIT - 1) / SPLIT;
        const int begin  = min(count, z * tpc * MB);
        const int end    = min(count, begin + tpc * MB);
        const int nloc   = end - begin;

        if (nloc > 0) {
            const float* Sp0 = g_S + ((size_t)e * CC + 2 * cp) * NPOS;
            const float* Sp1 = Sp0 + NPOS;
            const float* Qp0 = g_Q + ((size_t)e * CC + 2 * cp) * NSLOT;
            const float* Qp1 = Qp0 + NSLOT;
            const float* Lp0 = g_L + ((size_t)e * CC + 2 * cp) * NL;
            const float* Lp1 = Lp0 + NL;

            u64 kk[19];
            u64 q0, q1, q2 = 0;
            int a0, b0, a1, b1, a2 = 0, b2 = 0;
            if (w == 0) {
#pragma unroll
                for (int j = 0; j < 16; j++) kk[j] = pack2(Sp0[j * 32 + lane], Sp1[j * 32 + lane]);
#pragma unroll
                for (int j = 0; j < 3; j++)
                    kk[16 + j] = pack2(Sp0[992 + j * 32 + lane], Sp1[992 + j * 32 + lane]);
                q0 = pack2(Qp0[lane], Qp1[lane]);
                q1 = pack2(Qp0[96 + lane], Qp1[96 + lane]);
                slot_ab(lane, a0, b0);
                slot_ab(96 + lane, a1, b1);
            } else {
#pragma unroll
                for (int j = 0; j < 9; j++) kk[j] = pack2(Sp0[512 + j * 32 + lane], Sp1[512 + j * 32 + lane]);
#pragma unroll
                for (int j = 0; j < 6; j++) kk[9 + j] = pack2(Sp0[800 + j * 32 + lane], Sp1[800 + j * 32 + lane]);
                kk[15] = pack2(Sp0[1088 + lane], Sp1[1088 + lane]);
                kk[16] = (lane < NL) ? pack2(Lp0[lane], Lp1[lane]) : 0ULL;
                q0 = pack2(Qp0[32 + lane], Qp1[32 + lane]);
                q1 = pack2(Qp0[64 + lane], Qp1[64 + lane]);
                q2 = pack2(Qp0[128 + lane], Qp1[128 + lane]);
                slot_ab(32 + lane, a0, b0);
                slot_ab(64 + lane, a1, b1);
                if (128 + lane < NACT) slot_ab(128 + lane, a2, b2);
            }

            const int rowbase = goff + begin;
            const float* xTc = g_xT + ((size_t)cp * MAXN + rowbase) * 32;

            const int satm = t >> 2;
            const int sq   = t & 3;
            float4 xrA = make_float4(0.f, 0.f, 0.f, 0.f), xrB = xrA;
            if (satm < nloc) {
                const float4* rp = (const float4*)(xTc + (size_t)satm * 32);
                xrA = rp[sq]; xrB = rp[sq + 4];
            }

            const int mlane = ((lane >> 4) & 1) | (((lane >> 3) & 1) << 1)
                            | (((lane >> 2) & 1) << 2) | (((lane >> 1) & 1) << 3);
            const int xlin = lane & 15;

            for (int t0 = 0; t0 < nloc; t0 += MB) {
                const int rem = min(MB, nloc - t0);
                if (satm < rem) {
                    float4* sp = (float4*)xs[g][satm];
                    sp[sq] = xrA; sp[sq + 4] = xrB;
                }
                barsync64(1 + g);

                {
                    const int nxt = t0 + MB + satm;
                    if (nxt < nloc) {
                        const float4* rp = (const float4*)(xTc + (size_t)nxt * 32);
                        xrA = rp[sq]; xrB = rp[sq + 4];
                    }
                }

                u64 m0[8];
#pragma unroll
                for (int k = 0; k < 8; k++) {
                    u64 pv[2];
#pragma unroll
                    for (int h = 0; h < 2; h++) {
                        const int mm = 2 * k + h;
                        const ulonglong2* xv = (const ulonglong2*)xs[g][mm];
                        const u64* xrow = (const u64*)xs[g][mm];
                        u64 v;
                        if (w == 0) {
                            ulonglong2 P0 = xv[0], P1 = xv[1], P2 = xv[2], P3 = xv[3];
                            u64 G0 = q0;
                            G0 = fma2(kk[0],  P0.x, G0); G0 = fma2(kk[1],  P0.y, G0);
                            G0 = fma2(kk[2],  P1.x, G0); G0 = fma2(kk[3],  P1.y, G0);
                            ulonglong2 P4 = xv[4], P5 = xv[5];
                            G0 = fma2(kk[4],  P2.x, G0); G0 = fma2(kk[5],  P2.y, G0);
                            G0 = fma2(kk[6],  P3.x, G0); G0 = fma2(kk[7],  P3.y, G0);
                            ulonglong2 P6 = xv[6], P7 = xv[7];
                            G0 = fma2(kk[8],  P4.x, G0); G0 = fma2(kk[9],  P4.y, G0);
                            G0 = fma2(kk[10], P5.x, G0); G0 = fma2(kk[11], P5.y, G0);
                            G0 = fma2(kk[12], P6.x, G0); G0 = fma2(kk[13], P6.y, G0);
                            G0 = fma2(kk[14], P7.x, G0); G0 = fma2(kk[15], P7.y, G0);
                            u64 G1 = q1;
                            G1 = fma2(kk[16], P0.x, G1); G1 = fma2(kk[17], P0.y, G1);
                            G1 = fma2(kk[18], P1.x, G1);
                            const u64 pr0 = mul2(xrow[a0], xrow[b0]);
                            const u64 pr1 = mul2(xrow[a1], xrow[b1]);
                            v = fma2(G1, pr1, mul2(G0, pr0));
                        } else {
                            ulonglong2 P0 = xv[0], P1 = xv[1], P2 = xv[2], P3 = xv[3];
                            ulonglong2 P4 = xv[4];
                            u64 G0 = q0;
                            G0 = fma2(kk[0], P0.x, G0); G0 = fma2(kk[1], P0.y, G0);
                            G0 = fma2(kk[2], P1.x, G0); G0 = fma2(kk[3], P1.y, G0);
                            G0 = fma2(kk[4], P2.x, G0); G0 = fma2(kk[5], P2.y, G0);
                            G0 = fma2(kk[6], P3.x, G0); G0 = fma2(kk[7], P3.y, G0);
                            G0 = fma2(kk[8], P4.x, G0);
                            u64 G1 = q1;
                            G1 = fma2(kk[9],  P0.x, G1); G1 = fma2(kk[10], P0.y, G1);
                            G1 = fma2(kk[11], P1.x, G1); G1 = fma2(kk[12], P1.y, G1);
                            G1 = fma2(kk[13], P2.x, G1); G1 = fma2(kk[14], P2.y, G1);
                            const u64 G2 = fma2(kk[15], P0.x, q2);
                            const u64 lin = mul2(kk[16], xrow[xlin]);
                            const u64 pr0 = mul2(xrow[a0], xrow[b0]);
                            const u64 pr1 = mul2(xrow[a1], xrow[b1]);
                            const u64 pr2 = mul2(xrow[a2], xrow[b2]);
                            v = fma2(G0, pr0, fma2(G1, pr1, fma2(G2, pr2, lin)));
                        }
                        pv[h] = v;
                    }
                    const bool up = (lane & 16);
                    u64 mine = up ? pv[1] : pv[0];
                    u64 oth  = up ? pv[0] : pv[1];
                    m0[k] = add2(mine, __shfl_xor_sync(0xffffffffu, oth, 16));
                }
                u64 m1[4];
#pragma unroll
                for (int k = 0; k < 4; k++) {
                    const bool up = (lane & 8);
                    u64 mine = up ? m0[2 * k + 1] : m0[2 * k];
                    u64 oth  = up ? m0[2 * k]     : m0[2 * k + 1];
                    m1[k] = add2(mine, __shfl_xor_sync(0xffffffffu, oth, 8));
                }
                u64 m2[2];
#pragma unroll
                for (int k = 0; k < 2; k++) {
                    const bool up = (lane & 4);
                    u64 mine = up ? m1[2 * k + 1] : m1[2 * k];
                    u64 oth  = up ? m1[2 * k]     : m1[2 * k + 1];
                    m2[k] = add2(mine, __shfl_xor_sync(0xffffffffu, oth, 4));
                }
                {
                    const bool up = (lane & 2);
                    u64 mine = up ? m2[1] : m2[0];
                    u64 oth  = up ? m2[0] : m2[1];
                    u64 m3 = add2(mine, __shfl_xor_sync(0xffffffffu, oth, 2));
                    m3 = add2(m3, __shfl_xor_sync(0xffffffffu, m3, 1));
                    if ((lane & 1) == 0) red[g][mlane][w] = m3;
                }
                barsync64(1 + g);

                if (t < rem) {
                    const int id = g_binsg[rowbase + t0 + t];
                    *(u64*)(out + (size_t)id * CC + 2 * cp) = add2(red[g][t][0], red[g][t][1]);
                }
                barsync64(1 + g);
            }
        }

        // end-of-kernel: last contract block resets counters for next replay
        __syncthreads();
        if (tid == 0) {
            const int old = atomicAdd(&g_fin, 1);
            if (old == CONB - 1) {
                g_sym_done = 0; g_bin_done = 0; g_coeff_done = 0;
                g_trans_done = 0; g_fin = 0;
                __threadfence();
            }
        }
    }
}

// ---------------------------------------------------------------------------
extern "C" void kernel_launch(void* const* d_in, const int* in_sizes, int n_in,
                              void* d_out, int out_size) {
    const float* x  = (const float*)d_in[0];
    const int*   at = (const int*)d_in[1];
    const float* U3 = (const float*)d_in[2];
    const float* U2 = (const float*)d_in[3];
    const float* U1 = (const float*)d_in[4];
    const float* W3 = (const float*)d_in[5];
    const float* W2 = (const float*)d_in[6];
    const float* W1 = (const float*)d_in[7];
    float* out = (float*)d_out;
    const int N = in_sizes[1];

    const int grid = SYMB + 1 + PCB + N + CONB;
    fused_kernel<<<grid, 256>>>(U3, W3, U2, W2, U1, W1, x, at, out, N);
}

// round 12
// speedup vs baseline: 1.4515x; 1.4515x over previous
#include <cuda_runtime.h>

typedef unsigned long long u64;

#define NL    16
#define CC    128
#define CP    (CC / 2)
#define EE    10
#define P3C   23
#define P2C   4
#define MAXN  4096
#define MB    16
#define SPLIT 4
#define NPOS  1120
#define NSLOT 160
#define NACT  136
#define PCB   (CC / 8 * EE)
#define SYMB  ((NPOS * P3C + 255) / 256)   // 101

// __device__ globals = sanctioned scratch.
__device__ float g_S[(size_t)EE * CC * NPOS];
__device__ float g_Q[EE * CC * NSLOT];
__device__ float g_L[EE * CC * NL];
__device__ float g_U3S[NPOS * P3C];
__device__ __align__(16) float g_xT[(size_t)CP * MAXN * NL * 2]; // [cp][n][i][2ch], ORIGINAL atom order
__device__ int g_binsg[MAXN];
__device__ int g_counts[EE];
__device__ int g_offs[EE];

// ---- packed f32x2 helpers -------------------------------------------------
__device__ __forceinline__ u64 fma2(u64 a, u64 b, u64 c) {
    u64 d; asm("fma.rn.f32x2 %0, %1, %2, %3;" : "=l"(d) : "l"(a), "l"(b), "l"(c)); return d;
}
__device__ __forceinline__ u64 mul2(u64 a, u64 b) {
    u64 d; asm("mul.rn.f32x2 %0, %1, %2;" : "=l"(d) : "l"(a), "l"(b)); return d;
}
__device__ __forceinline__ u64 add2(u64 a, u64 b) {
    u64 d; asm("add.rn.f32x2 %0, %1, %2;" : "=l"(d) : "l"(a), "l"(b)); return d;
}
__device__ __forceinline__ u64 pack2(float lo, float hi) {
    u64 d; asm("mov.b64 %0, {%1, %2};" : "=l"(d) : "f"(lo), "f"(hi)); return d;
}

__device__ __forceinline__ void slot_ab(int s, int& a, int& b) {
    a = 0; b = 0;
    int off = 0;
#pragma unroll
    for (int aa = 15; aa >= 0; aa--) {
        int cnt = 16 - aa;
        if (s >= off && s < off + cnt) { a = aa; b = aa + (s - off); }
        off += cnt;
    }
}

__device__ __forceinline__ float u3at(const float* U3, int d0, int d1, int d2, int k) {
    return U3[((d0 * NL + d1) * NL + d2) * P3C + k];
}

// ---------------------------------------------------------------------------
// K1: sym-only (R8-validated: 4.48us). 256-thread pure map blocks.
// ---------------------------------------------------------------------------
__global__ __launch_bounds__(256) void k1_kernel(const float* __restrict__ U3) {
    const int idx = blockIdx.x * 256 + threadIdx.x;
    if (idx >= NPOS * P3C) return;
    const int p = idx / P3C;
    const int k = idx - p * P3C;
    int base, ch;
    if      (p < 512)  { ch = 0; base = 0;    }
    else if (p < 800)  { ch = 1; base = 512;  }
    else if (p < 992)  { ch = 2; base = 800;  }
    else if (p < 1088) { ch = 3; base = 992;  }
    else               { ch = 4; base = 1088; }
    const int rel = p - base;
    const int j = rel >> 5;
    const int l = rel & 31;
    const int s = ch * 32 + l;
    float val = 0.f;
    if (s < NACT) {
        int a, b; slot_ab(s, a, b);
        const int i = j;
        if (i <= a) {
            float sum = u3at(U3, i, a, b, k) + u3at(U3, i, b, a, k)
                      + u3at(U3, a, i, b, k) + u3at(U3, a, b, i, k)
                      + u3at(U3, b, i, a, k) + u3at(U3, b, a, i, k);
            float r = (i == a && a == b) ? 6.f : ((i == a || a == b) ? 2.f : 1.f);
            val = sum / r;
        }
    }
    g_U3S[idx] = val;
}

// ---------------------------------------------------------------------------
// K2: block 0 = binning (consumed only by K3); blocks [1,PCB] = coeff;
//     blocks [PCB+1, PCB+N] = transpose in ORIGINAL atom order (no bin dep).
// ---------------------------------------------------------------------------
__global__ __launch_bounds__(256) void k2_kernel(const float* __restrict__ W3,
                                                 const float* __restrict__ U2,
                                                 const float* __restrict__ W2,
                                                 const float* __restrict__ U1,
                                                 const float* __restrict__ W1,
                                                 const float* __restrict__ x,
                                                 const int* __restrict__ at, int N) {
    __shared__ float sm[NL * 132];
    const int tid = threadIdx.x;

    if (blockIdx.x == 0) {
        // ---- binning block (match_any; only K3 consumes outputs) ----
        __shared__ int ts[MAXN];
        __shared__ int wcnt[8 * EE];
        __shared__ int cur[8 * EE];
        const int w = tid >> 5, lane = tid & 31;
        for (int idx = tid; idx < N; idx += 256) ts[idx] = at[idx];
        if (tid < 8 * EE) wcnt[tid] = 0;
        __syncthreads();
        const int D  = (((N + 7) / 8) + 31) & ~31;
        const int lo = w * D, hi = min(N, lo + D);
        for (int base = lo; base < hi; base += 32) {
            const int idx = base + lane;
            const int t = (idx < hi) ? ts[idx] : -1;
            unsigned mm = __match_any_sync(0xffffffffu, t);
            if (t >= 0 && lane == (__ffs(mm) - 1))
                atomicAdd(&wcnt[w * EE + t], __popc(mm));
        }
        __syncthreads();
        if (tid == 0) {
            int acc = 0;
            for (int t = 0; t < EE; t++) {
                g_offs[t] = acc;
                int run = acc;
                for (int ww = 0; ww < 8; ww++) { cur[ww * EE + t] = run; run += wcnt[ww * EE + t]; }
                g_counts[t] = run - acc;
                acc = run;
            }
        }
        __syncthreads();
        for (int base = lo; base < hi; base += 32) {
            const int idx = base + lane;
            const int t = (idx < hi) ? ts[idx] : -1;
            unsigned mm = __match_any_sync(0xffffffffu, t);
            const int leader = __ffs(mm) - 1;
            const int rank = __popc(mm & ((1u << lane) - 1u));
            int baseoff = 0;
            if (t >= 0 && lane == leader) baseoff = atomicAdd(&cur[w * EE + t], __popc(mm));
            baseoff = __shfl_sync(0xffffffffu, baseoff, leader);
            if (t >= 0) g_binsg[baseoff + rank] = idx;
        }
        return;
    }

    if (blockIdx.x <= PCB) {
        const int bc = blockIdx.x - 1;
        const int c0 = (bc & 15) * 8;
        const int e  = bc >> 4;
        float* W3s = sm;
        float* W2s = sm + P3C * 8;
        float* W1s = W2s + P2C * 8;
        for (int idx = tid; idx < P3C * 8; idx += 256) {
            int k = idx >> 3, cl = idx & 7;
            W3s[idx] = W3[(e * P3C + k) * CC + c0 + cl];
        }
        if (tid < P2C * 8) {
            int k = tid >> 3, cl = tid & 7;
            W2s[tid] = W2[(e * P2C + k) * CC + c0 + cl];
        }
        if (tid < 8) W1s[tid] = W1[e * CC + c0 + tid];
        __syncthreads();

        for (int p = tid; p < NPOS; p += 256) {
            float u[P3C];
#pragma unroll
            for (int k = 0; k < P3C; k++) u[k] = g_U3S[p * P3C + k];
#pragma unroll
            for (int cl = 0; cl < 8; cl++) {
                float acc = 0.f;
#pragma unroll
                for (int k = 0; k < P3C; k++) acc += u[k] * W3s[k * 8 + cl];
                g_S[((size_t)(e * CC + c0 + cl)) * NPOS + p] = acc;
            }
        }
        if (tid < NSLOT) {
            const int s = tid;
            int a = 0, b = 0;
            const bool act = (s < NACT);
            if (act) slot_ab(s, a, b);
#pragma unroll
            for (int cl = 0; cl < 8; cl++) {
                float q = 0.f;
                if (act) {
                    float Bab = 0.f, Bba = 0.f;
#pragma unroll
                    for (int k = 0; k < P2C; k++) {
                        Bab += U2[(a * NL + b) * P2C + k] * W2s[k * 8 + cl];
                        Bba += U2[(b * NL + a) * P2C + k] * W2s[k * 8 + cl];
                    }
                    q = (a == b) ? Bab : (Bab + Bba);
                }
                g_Q[(size_t)(e * CC + c0 + cl) * NSLOT + s] = q;
            }
        }
        if (tid < NL) {
#pragma unroll
            for (int cl = 0; cl < 8; cl++)
                g_L[(size_t)(e * CC + c0 + cl) * NL + tid] = U1[tid] * W1s[cl];
        }
        return;
    }

    // ---- transpose block: one atom, original order (gp = n) ----
    const int n = blockIdx.x - PCB - 1;
    if (n >= N) return;
    const float4* xin = (const float4*)(x + (size_t)n * NL * CC);
#pragma unroll
    for (int q = 0; q < 2; q++) {
        const int v  = q * 256 + tid;
        const int i  = v >> 5;
        const int f4 = v & 31;
        *(float4*)(sm + i * 132 + f4 * 4) = xin[v];
    }
    __syncthreads();
    const int cp = tid >> 2;
    const int q  = tid & 3;
    const int c0 = 2 * cp;
    float* orow = g_xT + ((size_t)cp * MAXN + n) * 32 + q * 8;
    float4 oA, oB;
    oA.x = sm[(4 * q + 0) * 132 + c0]; oA.y = sm[(4 * q + 0) * 132 + c0 + 1];
    oA.z = sm[(4 * q + 1) * 132 + c0]; oA.w = sm[(4 * q + 1) * 132 + c0 + 1];
    oB.x = sm[(4 * q + 2) * 132 + c0]; oB.y = sm[(4 * q + 2) * 132 + c0 + 1];
    oB.z = sm[(4 * q + 3) * 132 + c0]; oB.w = sm[(4 * q + 3) * 132 + c0 + 1];
    ((float4*)orow)[0] = oA;
    ((float4*)orow)[1] = oB;
}

// ---------------------------------------------------------------------------
// K3: packed-f32x2 contraction (R9-identical math), rows gathered through
//     g_binsg (broadcast LDG per staged row, hidden by prefetch).
// ---------------------------------------------------------------------------
__global__ __launch_bounds__(64) void contract_kernel(float* __restrict__ out) {
    const int cp = blockIdx.x, e = blockIdx.y, z = blockIdx.z;
    const int t = threadIdx.x;
    const int w = t >> 5, lane = t & 31;

    __shared__ __align__(16) float xs[MB][32];
    __shared__ u64 red[MB][2];

    const int count  = g_counts[e];
    const int goff   = g_offs[e];
    const int ntiles = (count + MB - 1) / MB;
    const int tpc    = (ntiles + SPLIT - 1) / SPLIT;
    const int begin  = min(count, z * tpc * MB);
    const int end    = min(count, begin + tpc * MB);
    const int nloc   = end - begin;
    if (nloc <= 0) return;

    const float* Sp0 = g_S + ((size_t)e * CC + 2 * cp) * NPOS;
    const float* Sp1 = Sp0 + NPOS;
    const float* Qp0 = g_Q + ((size_t)e * CC + 2 * cp) * NSLOT;
    const float* Qp1 = Qp0 + NSLOT;
    const float* Lp0 = g_L + ((size_t)e * CC + 2 * cp) * NL;
    const float* Lp1 = Lp0 + NL;

    u64 kk[19];
    u64 q0, q1, q2 = 0;
    int a0, b0, a1, b1, a2 = 0, b2 = 0;
    if (w == 0) {
#pragma unroll
        for (int j = 0; j < 16; j++) kk[j] = pack2(Sp0[j * 32 + lane], Sp1[j * 32 + lane]);
#pragma unroll
        for (int j = 0; j < 3; j++)
            kk[16 + j] = pack2(Sp0[992 + j * 32 + lane], Sp1[992 + j * 32 + lane]);
        q0 = pack2(Qp0[lane], Qp1[lane]);
        q1 = pack2(Qp0[96 + lane], Qp1[96 + lane]);
        slot_ab(lane, a0, b0);
        slot_ab(96 + lane, a1, b1);
    } else {
#pragma unroll
        for (int j = 0; j < 9; j++) kk[j] = pack2(Sp0[512 + j * 32 + lane], Sp1[512 + j * 32 + lane]);
#pragma unroll
        for (int j = 0; j < 6; j++) kk[9 + j] = pack2(Sp0[800 + j * 32 + lane], Sp1[800 + j * 32 + lane]);
        kk[15] = pack2(Sp0[1088 + lane], Sp1[1088 + lane]);
        kk[16] = (lane < NL) ? pack2(Lp0[lane], Lp1[lane]) : 0ULL;
        q0 = pack2(Qp0[32 + lane], Qp1[32 + lane]);
        q1 = pack2(Qp0[64 + lane], Qp1[64 + lane]);
        q2 = pack2(Qp0[128 + lane], Qp1[128 + lane]);
        slot_ab(32 + lane, a0, b0);
        slot_ab(64 + lane, a1, b1);
        if (128 + lane < NACT) slot_ab(128 + lane, a2, b2);
    }

    const int rowbase = goff + begin;
    const float* xTc = g_xT + (size_t)cp * MAXN * 32;   // original-order plane
    const int* bins  = g_binsg + rowbase;

    const int satm = t >> 2;
    const int sq   = t & 3;
    float4 xrA = make_float4(0.f, 0.f, 0.f, 0.f), xrB = xrA;
    if (satm < nloc) {
        const int row = bins[satm];                       // broadcast within quad
        const float4* rp = (const float4*)(xTc + (size_t)row * 32);
        xrA = rp[sq]; xrB = rp[sq + 4];
    }

    const int mlane = ((lane >> 4) & 1) | (((lane >> 3) & 1) << 1)
                    | (((lane >> 2) & 1) << 2) | (((lane >> 1) & 1) << 3);
    const int xlin = lane & 15;

    for (int t0 = 0; t0 < nloc; t0 += MB) {
        const int rem = min(MB, nloc - t0);
        if (satm < rem) {
            float4* sp = (float4*)xs[satm];
            sp[sq] = xrA; sp[sq + 4] = xrB;
        }
        __syncthreads();

        {
            const int nxt = t0 + MB + satm;
            if (nxt < nloc) {
                const int row = bins[nxt];
                const float4* rp = (const float4*)(xTc + (size_t)row * 32);
                xrA = rp[sq]; xrB = rp[sq + 4];
            }
        }

        u64 m0[8];
#pragma unroll
        for (int k = 0; k < 8; k++) {
            u64 pv[2];
#pragma unroll
            for (int h = 0; h < 2; h++) {
                const int mm = 2 * k + h;
                const ulonglong2* xv = (const ulonglong2*)xs[mm];
                const u64* xrow = (const u64*)xs[mm];
                u64 v;
                if (w == 0) {
                    ulonglong2 P0 = xv[0], P1 = xv[1], P2 = xv[2], P3 = xv[3];
                    u64 G0 = q0;
                    G0 = fma2(kk[0],  P0.x, G0); G0 = fma2(kk[1],  P0.y, G0);
                    G0 = fma2(kk[2],  P1.x, G0); G0 = fma2(kk[3],  P1.y, G0);
                    ulonglong2 P4 = xv[4], P5 = xv[5];
                    G0 = fma2(kk[4],  P2.x, G0); G0 = fma2(kk[5],  P2.y, G0);
                    G0 = fma2(kk[6],  P3.x, G0); G0 = fma2(kk[7],  P3.y, G0);
                    ulonglong2 P6 = xv[6], P7 = xv[7];
                    G0 = fma2(kk[8],  P4.x, G0); G0 = fma2(kk[9],  P4.y, G0);
                    G0 = fma2(kk[10], P5.x, G0); G0 = fma2(kk[11], P5.y, G0);
                    G0 = fma2(kk[12], P6.x, G0); G0 = fma2(kk[13], P6.y, G0);
                    G0 = fma2(kk[14], P7.x, G0); G0 = fma2(kk[15], P7.y, G0);
                    u64 G1 = q1;
                    G1 = fma2(kk[16], P0.x, G1); G1 = fma2(kk[17], P0.y, G1);
                    G1 = fma2(kk[18], P1.x, G1);
                    const u64 pr0 = mul2(xrow[a0], xrow[b0]);
                    const u64 pr1 = mul2(xrow[a1], xrow[b1]);
                    v = fma2(G1, pr1, mul2(G0, pr0));
                } else {
                    ulonglong2 P0 = xv[0], P1 = xv[1], P2 = xv[2], P3 = xv[3];
                    ulonglong2 P4 = xv[4];
                    u64 G0 = q0;
                    G0 = fma2(kk[0], P0.x, G0); G0 = fma2(kk[1], P0.y, G0);
                    G0 = fma2(kk[2], P1.x, G0); G0 = fma2(kk[3], P1.y, G0);
                    G0 = fma2(kk[4], P2.x, G0); G0 = fma2(kk[5], P2.y, G0);
                    G0 = fma2(kk[6], P3.x, G0); G0 = fma2(kk[7], P3.y, G0);
                    G0 = fma2(kk[8], P4.x, G0);
                    u64 G1 = q1;
                    G1 = fma2(kk[9],  P0.x, G1); G1 = fma2(kk[10], P0.y, G1);
                    G1 = fma2(kk[11], P1.x, G1); G1 = fma2(kk[12], P1.y, G1);
                    G1 = fma2(kk[13], P2.x, G1); G1 = fma2(kk[14], P2.y, G1);
                    const u64 G2 = fma2(kk[15], P0.x, q2);
                    const u64 lin = mul2(kk[16], xrow[xlin]);
                    const u64 pr0 = mul2(xrow[a0], xrow[b0]);
                    const u64 pr1 = mul2(xrow[a1], xrow[b1]);
                    const u64 pr2 = mul2(xrow[a2], xrow[b2]);
                    v = fma2(G0, pr0, fma2(G1, pr1, fma2(G2, pr2, lin)));
                }
                pv[h] = v;
            }
            const bool up = (lane & 16);
            u64 mine = up ? pv[1] : pv[0];
            u64 oth  = up ? pv[0] : pv[1];
            m0[k] = add2(mine, __shfl_xor_sync(0xffffffffu, oth, 16));
        }
        u64 m1[4];
#pragma unroll
        for (int k = 0; k < 4; k++) {
            const bool up = (lane & 8);
            u64 mine = up ? m0[2 * k + 1] : m0[2 * k];
            u64 oth  = up ? m0[2 * k]     : m0[2 * k + 1];
            m1[k] = add2(mine, __shfl_xor_sync(0xffffffffu, oth, 8));
        }
        u64 m2[2];
#pragma unroll
        for (int k = 0; k < 2; k++) {
            const bool up = (lane & 4);
            u64 mine = up ? m1[2 * k + 1] : m1[2 * k];
            u64 oth  = up ? m1[2 * k]     : m1[2 * k + 1];
            m2[k] = add2(mine, __shfl_xor_sync(0xffffffffu, oth, 4));
        }
        {
            const bool up = (lane & 2);
            u64 mine = up ? m2[1] : m2[0];
            u64 oth  = up ? m2[0] : m2[1];
            u64 m3 = add2(mine, __shfl_xor_sync(0xffffffffu, oth, 2));
            m3 = add2(m3, __shfl_xor_sync(0xffffffffu, m3, 1));
            if ((lane & 1) == 0) red[mlane][w] = m3;
        }
        __syncthreads();

        if (t < rem) {
            const int id = bins[t0 + t];
            *(u64*)(out + (size_t)id * CC + 2 * cp) = add2(red[t][0], red[t][1]);
        }
        __syncthreads();
    }
}

// ---------------------------------------------------------------------------
extern "C" void kernel_launch(void* const* d_in, const int* in_sizes, int n_in,
                              void* d_out, int out_size) {
    const float* x  = (const float*)d_in[0];
    const int*   at = (const int*)d_in[1];
    const float* U3 = (const float*)d_in[2];
    const float* U2 = (const float*)d_in[3];
    const float* U1 = (const float*)d_in[4];
    const float* W3 = (const float*)d_in[5];
    const float* W2 = (const float*)d_in[6];
    const float* W1 = (const float*)d_in[7];
    float* out = (float*)d_out;
    const int N = in_sizes[1];

    k1_kernel<<<SYMB, 256>>>(U3);
    k2_kernel<<<1 + PCB + N, 256>>>(W3, U2, W2, U1, W1, x, at, N);
    contract_kernel<<<dim3(CP, EE, SPLIT), 64>>>(out);
}